// round 9
// baseline (speedup 1.0000x reference)
#include <cuda_runtime.h>
#include <cuda_bf16.h>
#include <cstdint>

#define Bsz 8
#define Nn 2048
#define Fd 256
#define KC 32
#define NIT (Nn / KC)   // 64 chunks per pass

// -------- device scratch (no allocation allowed) --------
__device__ float g_Wh[(size_t)Bsz * Nn * Fd];      // used only as Y1 spill scratch
__device__ float g_S1[Bsz * Nn];
__device__ float g_S2[Bsz * Nn];
__device__ float g_E1p[Bsz * Nn];
__device__ float g_E1n[Bsz * Nn];
__device__ float g_E2p[Bsz * Nn];
__device__ float g_E2n[Bsz * Nn];
__device__ float g_Z1[Bsz * Nn];
__device__ float g_Z2[Bsz * Nn];
// X arrays, layout [b][j][f], bf16
__device__ unsigned short g_X1h[(size_t)Bsz * Nn * Fd];
__device__ unsigned short g_X1l[(size_t)Bsz * Nn * Fd];
__device__ unsigned short g_X2h[(size_t)Bsz * Nn * Fd];
__device__ unsigned short g_X2l[(size_t)Bsz * Nn * Fd];
// packed bit masks: [row][64] u32; word w = s*4+t holds bit l = mask at
// j = s*128 + 4*l + t
__device__ uint32_t g_M1[(size_t)Bsz * Nn * 64];
__device__ uint32_t g_M2[(size_t)Bsz * Nn * 64];

// -------- helpers --------
__device__ __forceinline__ uint32_t smem_u32(const void* p) {
    uint32_t a;
    asm("{ .reg .u64 t; cvta.to.shared.u64 t, %1; cvt.u32.u64 %0, t; }" : "=r"(a) : "l"(p));
    return a;
}
__device__ __forceinline__ void cp_async16(uint32_t dst, const void* src) {
    asm volatile("cp.async.cg.shared.global [%0], [%1], 16;" :: "r"(dst), "l"(src) : "memory");
}
__device__ __forceinline__ void cp_commit() {
    asm volatile("cp.async.commit_group;" ::: "memory");
}
__device__ __forceinline__ void cp_wait1() {
    asm volatile("cp.async.wait_group 1;" ::: "memory");
}
__device__ __forceinline__ void ldsm4(uint32_t* r, uint32_t addr) {
    asm volatile("ldmatrix.sync.aligned.m8n8.x4.shared.b16 {%0,%1,%2,%3}, [%4];"
                 : "=r"(r[0]), "=r"(r[1]), "=r"(r[2]), "=r"(r[3]) : "r"(addr));
}
__device__ __forceinline__ void ldsm4t(uint32_t* r, uint32_t addr) {
    asm volatile("ldmatrix.sync.aligned.m8n8.x4.trans.shared.b16 {%0,%1,%2,%3}, [%4];"
                 : "=r"(r[0]), "=r"(r[1]), "=r"(r[2]), "=r"(r[3]) : "r"(addr));
}
__device__ __forceinline__ void mma16816(float* d, const uint32_t* a, uint32_t b0, uint32_t b1) {
    asm volatile(
        "mma.sync.aligned.m16n8k16.row.col.f32.bf16.bf16.f32 "
        "{%0,%1,%2,%3}, {%4,%5,%6,%7}, {%8,%9}, {%0,%1,%2,%3};"
        : "+f"(d[0]), "+f"(d[1]), "+f"(d[2]), "+f"(d[3])
        : "r"(a[0]), "r"(a[1]), "r"(a[2]), "r"(a[3]), "r"(b0), "r"(b1));
}
__device__ __forceinline__ uint32_t bf16pair(float lo, float hi) {
    uint32_t r;
    asm("cvt.rn.bf16x2.f32 %0, %1, %2;" : "=r"(r) : "f"(hi), "f"(lo));
    return r;
}

// ---------------------------------------------------------------------------
// K1: fused  Wh = h@W  ->  s1,s2,exps  ->  X1/X2 hi/lo bf16 split
//     CTA: 64 rows x 256 cols, 256 threads; Wh never written to DRAM
// ---------------------------------------------------------------------------
__global__ __launch_bounds__(256) void gemmX_kernel(const float* __restrict__ h,
                                                    const float* __restrict__ W,
                                                    const float* __restrict__ a) {
    __shared__ float As[16][68];     // [k][i]
    __shared__ float Bs[16][256];    // [k][f]
    __shared__ float a_s[512];

    int tid = threadIdx.x;
    int i0 = blockIdx.x * 64;
    int tx = tid & 15;      // cols tx*16 .. +15
    int ty = tid >> 4;      // rows ty*4 .. +3

    a_s[tid] = a[tid];
    a_s[256 + tid] = a[256 + tid];

    float acc[4][16];
#pragma unroll
    for (int ii = 0; ii < 4; ii++)
#pragma unroll
        for (int jj = 0; jj < 16; jj++) acc[ii][jj] = 0.f;

    for (int k0 = 0; k0 < 256; k0 += 16) {
        {
            int r = tid >> 2, c4 = (tid & 3) * 4;
            float4 v = *(const float4*)&h[(size_t)(i0 + r) * 256 + k0 + c4];
            As[c4 + 0][r] = v.x; As[c4 + 1][r] = v.y;
            As[c4 + 2][r] = v.z; As[c4 + 3][r] = v.w;
        }
#pragma unroll
        for (int r = 0; r < 4; r++) {
            int idx = tid + r * 256;
            int row = idx >> 6, c4 = (idx & 63) * 4;
            *(float4*)&Bs[row][c4] = *(const float4*)&W[(size_t)(k0 + row) * 256 + c4];
        }
        __syncthreads();
#pragma unroll
        for (int k = 0; k < 16; k++) {
            float4 av4 = *(const float4*)&As[k][ty * 4];
            float av[4] = {av4.x, av4.y, av4.z, av4.w};
            float bv[16];
#pragma unroll
            for (int m = 0; m < 4; m++) {
                float4 b4 = *(const float4*)&Bs[k][tx * 16 + m * 4];
                bv[m * 4 + 0] = b4.x; bv[m * 4 + 1] = b4.y;
                bv[m * 4 + 2] = b4.z; bv[m * 4 + 3] = b4.w;
            }
#pragma unroll
            for (int ii = 0; ii < 4; ii++)
#pragma unroll
                for (int jj = 0; jj < 16; jj++) acc[ii][jj] += av[ii] * bv[jj];
        }
        __syncthreads();
    }

    // scores: s1,s2 per row (reduce over 16 lanes that share the row group)
    float s1v[4], s2v[4];
#pragma unroll
    for (int ii = 0; ii < 4; ii++) {
        float p1 = 0.f, p2 = 0.f;
#pragma unroll
        for (int jj = 0; jj < 16; jj++) {
            p1 += acc[ii][jj] * a_s[tx * 16 + jj];
            p2 += acc[ii][jj] * a_s[256 + tx * 16 + jj];
        }
#pragma unroll
        for (int o = 8; o; o >>= 1) {
            p1 += __shfl_xor_sync(0xffffffffu, p1, o);
            p2 += __shfl_xor_sync(0xffffffffu, p2, o);
        }
        s1v[ii] = p1; s2v[ii] = p2;
    }

#pragma unroll
    for (int ii = 0; ii < 4; ii++) {
        int row = i0 + ty * 4 + ii;
        float e2p = expf(s2v[ii]);
        float e2n = expf(0.2f * s2v[ii]);
        if (tx == 0) {
            g_S1[row] = s1v[ii];
            g_S2[row] = s2v[ii];
            g_E1p[row] = expf(s1v[ii]);
            g_E1n[row] = expf(0.2f * s1v[ii]);
            g_E2p[row] = e2p;
            g_E2n[row] = e2n;
        }
        size_t base = (size_t)row * 256 + tx * 16;
#pragma unroll
        for (int m = 0; m < 4; m++) {
            float x1[4], x2[4], h1[4], h2[4];
#pragma unroll
            for (int t = 0; t < 4; t++) {
                float v = acc[ii][m * 4 + t];
                x1[t] = v * e2p;
                x2[t] = v * e2n;
                h1[t] = __bfloat162float(__float2bfloat16(x1[t]));
                h2[t] = __bfloat162float(__float2bfloat16(x2[t]));
            }
            uint2 o1h, o1l, o2h, o2l;
            o1h.x = bf16pair(h1[0], h1[1]); o1h.y = bf16pair(h1[2], h1[3]);
            o1l.x = bf16pair(x1[0] - h1[0], x1[1] - h1[1]);
            o1l.y = bf16pair(x1[2] - h1[2], x1[3] - h1[3]);
            o2h.x = bf16pair(h2[0], h2[1]); o2h.y = bf16pair(h2[2], h2[3]);
            o2l.x = bf16pair(x2[0] - h2[0], x2[1] - h2[1]);
            o2l.y = bf16pair(x2[2] - h2[2], x2[3] - h2[3]);
            *(uint2*)&g_X1h[base + m * 4] = o1h;
            *(uint2*)&g_X1l[base + m * 4] = o1l;
            *(uint2*)&g_X2h[base + m * 4] = o2h;
            *(uint2*)&g_X2l[base + m * 4] = o2l;
        }
    }
}

// ---------------------------------------------------------------------------
// K2: packed bit masks + Z sums, vectorized (one warp per row, 4 j/lane/step)
// ---------------------------------------------------------------------------
__global__ __launch_bounds__(256) void mask_kernel(const float* __restrict__ adj) {
    int row = blockIdx.x * 8 + (threadIdx.x >> 5);
    int lane = threadIdx.x & 31;
    int b = row >> 11;
    const float4* ar  = (const float4*)(adj + (size_t)row * Nn);
    const float4* s2g = (const float4*)(g_S2 + b * Nn);
    const float4* epg = (const float4*)(g_E2p + b * Nn);
    const float4* eng = (const float4*)(g_E2n + b * Nn);
    float ns1 = -g_S1[row];
    float z1 = 0.f, z2 = 0.f;
    uint32_t w1lo = 0, w1hi = 0, w2lo = 0, w2hi = 0;
#pragma unroll 2
    for (int s = 0; s < 16; s++) {
        int q = s * 32 + lane;
        float4 av = ar[q];
        float4 sv = s2g[q];
        float4 pv = epg[q];
        float4 nv = eng[q];
        float avv[4] = {av.x, av.y, av.z, av.w};
        float svv[4] = {sv.x, sv.y, sv.z, sv.w};
        float pvv[4] = {pv.x, pv.y, pv.z, pv.w};
        float nvv[4] = {nv.x, nv.y, nv.z, nv.w};
        bool m1[4], m2[4];
#pragma unroll
        for (int t = 0; t < 4; t++) {
            bool on = avv[t] > 0.5f;
            bool pos = svv[t] > ns1;
            m1[t] = on && pos;
            m2[t] = on && !pos;
            if (m1[t]) z1 += pvv[t];
            if (m2[t]) z2 += nvv[t];
        }
#pragma unroll
        for (int t = 0; t < 4; t++) {
            uint32_t b1 = __ballot_sync(0xffffffffu, m1[t]);
            uint32_t b2 = __ballot_sync(0xffffffffu, m2[t]);
            int w = s * 4 + t;
            if (lane == (w & 31)) {
                if (w < 32) { w1lo = b1; w2lo = b2; }
                else        { w1hi = b1; w2hi = b2; }
            }
        }
    }
#pragma unroll
    for (int o = 16; o; o >>= 1) {
        z1 += __shfl_xor_sync(0xffffffffu, z1, o);
        z2 += __shfl_xor_sync(0xffffffffu, z2, o);
    }
    g_M1[(size_t)row * 64 + lane] = w1lo;
    g_M1[(size_t)row * 64 + 32 + lane] = w1hi;
    g_M2[(size_t)row * 64 + lane] = w2lo;
    g_M2[(size_t)row * 64 + 32 + lane] = w2hi;
    if (lane == 0) { g_Z1[row] = z1; g_Z2[row] = z2; }
}

// ---------------------------------------------------------------------------
// K3: HMMA masked attention + LayerNorm + exact GELU
//     CTA: 128 rows x 256 f, 512 threads, 16 warps (32x64 warp tiles)
//     3 X slots: write(chunk c) and prior reader MMA(c-3) are barrier-separated
// ---------------------------------------------------------------------------
#define ROWS 128
#define XS_STRIDE 260
#define SLOT_BYTES 32768                    // hi(16K)+lo(16K)
#define MEXP0 (3 * SLOT_BYTES)              // 98304
#define MSTRIDE 80
#define MEXP1 (MEXP0 + ROWS * MSTRIDE)      // 108544
#define PACKED_OFF (MEXP1 + ROWS * MSTRIDE) // 118784 (+32KB -> 151552)
#define DYN_B (PACKED_OFF + 32768)          // 151552 (xs overlay 133120 fits)

__global__ void __launch_bounds__(512, 1)
attn_mma_kernel(const float* __restrict__ gamma, const float* __restrict__ beta,
                float* __restrict__ out) {
    extern __shared__ char dyn[];
    __shared__ float e1p_s[ROWS], e1n_s[ROWS], invz_s[ROWS], mu_s[ROWS], rs_s[ROWS];

    const int tid = threadIdx.x;
    const int lane = tid & 31;
    const int wid = tid >> 5;
    const int wm = wid >> 2, wn = wid & 3;
    const int b = blockIdx.y;
    const int i0 = blockIdx.x * ROWS;

    const uint32_t smem = smem_u32(dyn);
    float* xs = (float*)dyn;
    uint32_t* packed_s = (uint32_t*)(dyn + PACKED_OFF);

    if (tid < ROWS) {
        float e1p = g_E1p[b * Nn + i0 + tid];
        float e1n = g_E1n[b * Nn + i0 + tid];
        e1p_s[tid] = e1p;
        e1n_s[tid] = e1n;
        invz_s[tid] = 1.f / (e1p * g_Z1[b * Nn + i0 + tid] +
                             e1n * g_Z2[b * Nn + i0 + tid]);
    }

    // ldmatrix per-lane address components (proven layout)
    const uint32_t aRowOff = (uint32_t)((32 * wm + ((lane >> 3) & 1) * 8 + (lane & 7)) * MSTRIDE
                                        + (lane >> 4) * 16);
    const int jb = ((lane >> 3) & 1) * 8 + (lane & 7);
    const int ub = 8 * wn + (lane >> 4);
    const int jsw = jb & 7;

    const int mi = tid >> 2;        // 0..127
    const int mq = tid & 3;
    const uint32_t mstRel = (uint32_t)(mi * MSTRIDE + mq * 16);

    const int r0 = 32 * wm + (lane >> 2);
    const int cb = 64 * wn + (lane & 3) * 2;
    float* gy = g_Wh + ((size_t)b * Nn + i0) * Fd;   // Y1 spill scratch

    float dacc[2][8][4];

#pragma unroll 1
    for (int pass = 0; pass < 2; pass++) {
        const unsigned short* srcH =
            (pass == 0 ? g_X1h : g_X2h) + (size_t)b * Nn * Fd;
        const unsigned short* srcL =
            (pass == 0 ? g_X1l : g_X2l) + (size_t)b * Nn * Fd;
        const uint32_t* gM =
            (pass == 0 ? g_M1 : g_M2) + (size_t)(b * Nn + i0) * 64;

#pragma unroll
        for (int mt = 0; mt < 2; mt++)
#pragma unroll
            for (int n8 = 0; n8 < 8; n8++)
#pragma unroll
                for (int k = 0; k < 4; k++) dacc[mt][n8][k] = 0.f;

        // load packed masks (8192 words = 2048 uint4)
#pragma unroll
        for (int r = 0; r < 4; r++) {
            int idx = tid + r * 512;
            *(uint4*)&packed_s[idx * 4] = ((const uint4*)gM)[idx];
        }

        // prologue cp: chunk 0 -> slot 0
#pragma unroll
        for (int r = 0; r < 2; r++) {
            int e = tid + r * 512;
            int j = e >> 5, u = e & 31;
            uint32_t d = smem + j * 512 + ((u ^ (j & 7)) << 4);
            cp_async16(d, srcH + (size_t)j * Fd + u * 8);
            cp_async16(d + 16384, srcL + (size_t)j * Fd + u * 8);
        }
        cp_commit();
        __syncthreads();   // packed masks visible

        // expand mask chunk 0 -> buf0
        {
            uint4 wv = *(const uint4*)&packed_s[mi * 64];
            uint32_t sh = (uint32_t)(mq << 1);
            uint32_t w0 = ((wv.x >> sh) & 1u) * 0x3F80u + ((wv.y >> sh) & 1u) * 0x3F800000u;
            uint32_t w1 = ((wv.z >> sh) & 1u) * 0x3F80u + ((wv.w >> sh) & 1u) * 0x3F800000u;
            uint32_t w2 = ((wv.x >> (sh + 1)) & 1u) * 0x3F80u + ((wv.y >> (sh + 1)) & 1u) * 0x3F800000u;
            uint32_t w3 = ((wv.z >> (sh + 1)) & 1u) * 0x3F80u + ((wv.w >> (sh + 1)) & 1u) * 0x3F800000u;
            asm volatile("st.shared.v4.b32 [%0], {%1,%2,%3,%4};"
                         :: "r"(smem + MEXP0 + mstRel), "r"(w0), "r"(w1), "r"(w2), "r"(w3) : "memory");
        }

        int cur = 0;   // slot of chunk it (it % 3)
#pragma unroll 1
        for (int it = 0; it < NIT; it++) {
            // issue X(it+1) into slot (it+1)%3
            if (it + 1 < NIT) {
                int nxt = cur + 1; if (nxt == 3) nxt = 0;
                uint32_t dst = smem + (uint32_t)nxt * SLOT_BYTES;
                size_t grow = (size_t)((it + 1) * KC) * Fd;
#pragma unroll
                for (int r = 0; r < 2; r++) {
                    int e = tid + r * 512;
                    int j = e >> 5, u = e & 31;
                    uint32_t d = dst + j * 512 + ((u ^ (j & 7)) << 4);
                    cp_async16(d, srcH + grow + (size_t)j * Fd + u * 8);
                    cp_async16(d + 16384, srcL + grow + (size_t)j * Fd + u * 8);
                }
            }
            cp_commit();
            cp_wait1();        // X(it) landed
            __syncthreads();   // mask(it) writes + X(it) visible to all

            // MMA on chunk it
            const uint32_t xb = smem + (uint32_t)cur * SLOT_BYTES;
            const uint32_t mbuf = smem + ((it & 1) ? MEXP1 : MEXP0);
#pragma unroll
            for (int ks = 0; ks < 2; ks++) {
                uint32_t a0[4], a1[4];
                ldsm4(a0, mbuf + aRowOff + ks * 32);
                ldsm4(a1, mbuf + aRowOff + 16 * MSTRIDE + ks * 32);
                const int j = jb + ks * 16;
                const uint32_t rowb = xb + j * 512;
#pragma unroll
                for (int ng = 0; ng < 4; ng++) {
                    const int u = ub + 2 * ng;
                    const uint32_t addrH = rowb + ((u ^ jsw) << 4);
                    uint32_t bh[4], bl[4];
                    ldsm4t(bh, addrH);
                    ldsm4t(bl, addrH + 16384);
                    mma16816(dacc[0][2 * ng],     a0, bh[0], bh[1]);
                    mma16816(dacc[0][2 * ng + 1], a0, bh[2], bh[3]);
                    mma16816(dacc[1][2 * ng],     a1, bh[0], bh[1]);
                    mma16816(dacc[1][2 * ng + 1], a1, bh[2], bh[3]);
                    mma16816(dacc[0][2 * ng],     a0, bl[0], bl[1]);
                    mma16816(dacc[0][2 * ng + 1], a0, bl[2], bl[3]);
                    mma16816(dacc[1][2 * ng],     a1, bl[0], bl[1]);
                    mma16816(dacc[1][2 * ng + 1], a1, bl[2], bl[3]);
                }
            }

            // expand mask(it+1) into the other buffer (its previous readers
            // finished before barrier(it))
            if (it + 1 < NIT) {
                int cc = it + 1;
                uint4 wv = *(const uint4*)&packed_s[mi * 64 + ((cc >> 2) << 2)];
                uint32_t sh = (uint32_t)(((cc & 3) << 3) + (mq << 1));
                uint32_t w0 = ((wv.x >> sh) & 1u) * 0x3F80u + ((wv.y >> sh) & 1u) * 0x3F800000u;
                uint32_t w1 = ((wv.z >> sh) & 1u) * 0x3F80u + ((wv.w >> sh) & 1u) * 0x3F800000u;
                uint32_t w2 = ((wv.x >> (sh + 1)) & 1u) * 0x3F80u + ((wv.y >> (sh + 1)) & 1u) * 0x3F800000u;
                uint32_t w3 = ((wv.z >> (sh + 1)) & 1u) * 0x3F80u + ((wv.w >> (sh + 1)) & 1u) * 0x3F800000u;
                uint32_t dst = smem + ((cc & 1) ? MEXP1 : MEXP0) + mstRel;
                asm volatile("st.shared.v4.b32 [%0], {%1,%2,%3,%4};"
                             :: "r"(dst), "r"(w0), "r"(w1), "r"(w2), "r"(w3) : "memory");
            }
            cur = cur + 1; if (cur == 3) cur = 0;
        }
        __syncthreads();   // all MMA reads + expands done before pass flip

        if (pass == 0) {
            // spill e1p*Y1 to global scratch (thread-private addresses)
#pragma unroll
            for (int mt = 0; mt < 2; mt++) {
                int ra = r0 + 16 * mt;
                float ea = e1p_s[ra], eb = e1p_s[ra + 8];
#pragma unroll
                for (int n8 = 0; n8 < 8; n8++) {
                    int c = cb + 8 * n8;
                    *(float2*)&gy[(size_t)ra * 256 + c] =
                        make_float2(ea * dacc[mt][n8][0], ea * dacc[mt][n8][1]);
                    *(float2*)&gy[(size_t)(ra + 8) * 256 + c] =
                        make_float2(eb * dacc[mt][n8][2], eb * dacc[mt][n8][3]);
                }
            }
        }
    }

    // combine: x = (gy + e1n*Y2) * invZ -> xs (overlays main-loop smem)
#pragma unroll
    for (int mt = 0; mt < 2; mt++) {
        int ra = r0 + 16 * mt;
        float ea = e1n_s[ra], eb = e1n_s[ra + 8];
        float iza = invz_s[ra], izb = invz_s[ra + 8];
#pragma unroll
        for (int n8 = 0; n8 < 8; n8++) {
            int c = cb + 8 * n8;
            float2 ya = *(const float2*)&gy[(size_t)ra * 256 + c];
            float2 yb = *(const float2*)&gy[(size_t)(ra + 8) * 256 + c];
            xs[ra * XS_STRIDE + c]     = (ya.x + ea * dacc[mt][n8][0]) * iza;
            xs[ra * XS_STRIDE + c + 1] = (ya.y + ea * dacc[mt][n8][1]) * iza;
            xs[(ra + 8) * XS_STRIDE + c]     = (yb.x + eb * dacc[mt][n8][2]) * izb;
            xs[(ra + 8) * XS_STRIDE + c + 1] = (yb.y + eb * dacc[mt][n8][3]) * izb;
        }
    }
    __syncthreads();

    // LayerNorm stats: 4 threads per row
    {
        int row = tid >> 2, q = tid & 3;
        const float* xr = &xs[row * XS_STRIDE + q * 64];
        float sum = 0.f, ssq = 0.f;
#pragma unroll 8
        for (int k = 0; k < 64; k++) { float v = xr[k]; sum += v; ssq += v * v; }
        sum += __shfl_xor_sync(0xffffffffu, sum, 1);
        sum += __shfl_xor_sync(0xffffffffu, sum, 2);
        ssq += __shfl_xor_sync(0xffffffffu, ssq, 1);
        ssq += __shfl_xor_sync(0xffffffffu, ssq, 2);
        if (q == 0) {
            float mu = sum * (1.f / 256.f);
            float var = fmaxf(ssq * (1.f / 256.f) - mu * mu, 0.f);
            mu_s[row] = mu;
            rs_s[row] = rsqrtf(var + 1e-5f);
        }
    }
    __syncthreads();

    // gamma/beta + exact GELU, coalesced store (128 rows x 64 float4 = 8192)
    float* outb = out + ((size_t)b * Nn + i0) * Fd;
#pragma unroll 1
    for (int r = 0; r < 16; r++) {
        int u = tid + r * 512;
        int i = u >> 6;
        int c4 = (u & 63) * 4;
        float mu = mu_s[i], rs = rs_s[i];
        float4 xv = *(const float4*)&xs[i * XS_STRIDE + c4];
        float4 g = *(const float4*)&gamma[c4];
        float4 be = *(const float4*)&beta[c4];
        float x[4] = {xv.x, xv.y, xv.z, xv.w};
        float gv[4] = {g.x, g.y, g.z, g.w};
        float bv[4] = {be.x, be.y, be.z, be.w};
        float ov[4];
#pragma unroll
        for (int e = 0; e < 4; e++) {
            float y = (x[e] - mu) * rs * gv[e] + bv[e];
            ov[e] = 0.5f * y * (1.f + erff(y * 0.7071067811865475f));
        }
        *(float4*)&outb[(size_t)i * 256 + c4] = make_float4(ov[0], ov[1], ov[2], ov[3]);
    }
}

// ---------------------------------------------------------------------------
extern "C" void kernel_launch(void* const* d_in, const int* in_sizes, int n_in,
                              void* d_out, int out_size) {
    const float* h     = (const float*)d_in[0];
    const float* adj   = (const float*)d_in[1];
    const float* W     = (const float*)d_in[2];
    const float* a     = (const float*)d_in[3];
    const float* gamma = (const float*)d_in[4];
    const float* beta  = (const float*)d_in[5];
    float* out = (float*)d_out;

    cudaFuncSetAttribute(attn_mma_kernel,
                         cudaFuncAttributeMaxDynamicSharedMemorySize, DYN_B);

    gemmX_kernel<<<256, 256>>>(h, W, a);
    mask_kernel<<<2048, 256>>>(adj);
    attn_mma_kernel<<<dim3(16, 8), 512, DYN_B>>>(gamma, beta, out);
}

// round 10
// speedup vs baseline: 1.2540x; 1.2540x over previous
#include <cuda_runtime.h>
#include <cuda_bf16.h>
#include <cstdint>

#define Bsz 8
#define Nn 2048
#define Fd 256
#define KC 32
#define NIT (Nn / KC)   // 64 chunks per pass

// -------- device scratch (no allocation allowed) --------
__device__ float g_Wh[(size_t)Bsz * Nn * Fd];      // Wh, later reused as Y1 spill
__device__ float g_S1[Bsz * Nn];
__device__ float g_S2[Bsz * Nn];
__device__ float g_E1p[Bsz * Nn];
__device__ float g_E1n[Bsz * Nn];
__device__ float g_E2p[Bsz * Nn];
__device__ float g_E2n[Bsz * Nn];
__device__ float g_Z1[Bsz * Nn];
__device__ float g_Z2[Bsz * Nn];
// X arrays, layout [b][j][f], bf16
__device__ unsigned short g_X1h[(size_t)Bsz * Nn * Fd];
__device__ unsigned short g_X1l[(size_t)Bsz * Nn * Fd];
__device__ unsigned short g_X2h[(size_t)Bsz * Nn * Fd];
__device__ unsigned short g_X2l[(size_t)Bsz * Nn * Fd];
// packed bit masks: [row][64] u32; word w = s*4+t holds bit l = mask at
// j = s*128 + 4*l + t
__device__ uint32_t g_M1[(size_t)Bsz * Nn * 64];
__device__ uint32_t g_M2[(size_t)Bsz * Nn * 64];

// -------- helpers --------
__device__ __forceinline__ uint32_t smem_u32(const void* p) {
    uint32_t a;
    asm("{ .reg .u64 t; cvta.to.shared.u64 t, %1; cvt.u32.u64 %0, t; }" : "=r"(a) : "l"(p));
    return a;
}
__device__ __forceinline__ void cp_async16(uint32_t dst, const void* src) {
    asm volatile("cp.async.cg.shared.global [%0], [%1], 16;" :: "r"(dst), "l"(src) : "memory");
}
__device__ __forceinline__ void cp_commit() {
    asm volatile("cp.async.commit_group;" ::: "memory");
}
__device__ __forceinline__ void cp_wait1() {
    asm volatile("cp.async.wait_group 1;" ::: "memory");
}
__device__ __forceinline__ void ldsm4(uint32_t* r, uint32_t addr) {
    asm volatile("ldmatrix.sync.aligned.m8n8.x4.shared.b16 {%0,%1,%2,%3}, [%4];"
                 : "=r"(r[0]), "=r"(r[1]), "=r"(r[2]), "=r"(r[3]) : "r"(addr));
}
__device__ __forceinline__ void ldsm4t(uint32_t* r, uint32_t addr) {
    asm volatile("ldmatrix.sync.aligned.m8n8.x4.trans.shared.b16 {%0,%1,%2,%3}, [%4];"
                 : "=r"(r[0]), "=r"(r[1]), "=r"(r[2]), "=r"(r[3]) : "r"(addr));
}
__device__ __forceinline__ void mma16816(float* d, const uint32_t* a, uint32_t b0, uint32_t b1) {
    asm volatile(
        "mma.sync.aligned.m16n8k16.row.col.f32.bf16.bf16.f32 "
        "{%0,%1,%2,%3}, {%4,%5,%6,%7}, {%8,%9}, {%0,%1,%2,%3};"
        : "+f"(d[0]), "+f"(d[1]), "+f"(d[2]), "+f"(d[3])
        : "r"(a[0]), "r"(a[1]), "r"(a[2]), "r"(a[3]), "r"(b0), "r"(b1));
}
__device__ __forceinline__ uint32_t bf16pair(float lo, float hi) {
    uint32_t r;
    asm("cvt.rn.bf16x2.f32 %0, %1, %2;" : "=r"(r) : "f"(hi), "f"(lo));
    return r;
}

// ---------------------------------------------------------------------------
// K1: Wh = h @ W  (fp32, known-good, at scalar-FFMA ceiling)
// ---------------------------------------------------------------------------
__global__ __launch_bounds__(256) void gemm1_kernel(const float* __restrict__ h,
                                                    const float* __restrict__ W) {
    __shared__ float As[16][68];
    __shared__ float Bs[16][64];
    int tid = threadIdx.x;
    int i0 = blockIdx.x * 64, f0 = blockIdx.y * 64;
    int tx = tid & 15, ty = tid >> 4;
    float acc[4][4] = {};
    for (int k0 = 0; k0 < 256; k0 += 16) {
        {
            int r = tid >> 2, c4 = (tid & 3) * 4;
            float4 v = *(const float4*)&h[(size_t)(i0 + r) * 256 + k0 + c4];
            As[c4 + 0][r] = v.x; As[c4 + 1][r] = v.y;
            As[c4 + 2][r] = v.z; As[c4 + 3][r] = v.w;
        }
        {
            int r = tid >> 4, c4 = (tid & 15) * 4;
            *(float4*)&Bs[r][c4] = *(const float4*)&W[(size_t)(k0 + r) * 256 + f0 + c4];
        }
        __syncthreads();
#pragma unroll
        for (int k = 0; k < 16; k++) {
            float4 a = *(const float4*)&As[k][ty * 4];
            float4 b = *(const float4*)&Bs[k][tx * 4];
            float av[4] = {a.x, a.y, a.z, a.w};
            float bv[4] = {b.x, b.y, b.z, b.w};
#pragma unroll
            for (int ii = 0; ii < 4; ii++)
#pragma unroll
                for (int jj = 0; jj < 4; jj++) acc[ii][jj] += av[ii] * bv[jj];
        }
        __syncthreads();
    }
#pragma unroll
    for (int ii = 0; ii < 4; ii++)
        *(float4*)&g_Wh[(size_t)(i0 + ty * 4 + ii) * 256 + f0 + tx * 4] =
            make_float4(acc[ii][0], acc[ii][1], acc[ii][2], acc[ii][3]);
}

// ---------------------------------------------------------------------------
// K2: scores + factored exps
// ---------------------------------------------------------------------------
__global__ __launch_bounds__(256) void score_kernel(const float* __restrict__ a) {
    int row = blockIdx.x * 8 + (threadIdx.x >> 5);
    int lane = threadIdx.x & 31;
    const float* wh = &g_Wh[(size_t)row * 256];
    float s1 = 0.f, s2 = 0.f;
#pragma unroll
    for (int c = 0; c < 8; c++) {
        int f = c * 32 + lane;
        float v = wh[f];
        s1 += v * a[f];
        s2 += v * a[256 + f];
    }
#pragma unroll
    for (int o = 16; o; o >>= 1) {
        s1 += __shfl_xor_sync(0xffffffffu, s1, o);
        s2 += __shfl_xor_sync(0xffffffffu, s2, o);
    }
    if (lane == 0) {
        g_S1[row] = s1; g_S2[row] = s2;
        g_E1p[row] = expf(s1);  g_E1n[row] = expf(0.2f * s1);
        g_E2p[row] = expf(s2);  g_E2n[row] = expf(0.2f * s2);
    }
}

// ---------------------------------------------------------------------------
// K3: X1/X2 hi/lo bf16 split (4096 blocks x 256 thr)
// ---------------------------------------------------------------------------
__global__ __launch_bounds__(256) void buildX_kernel() {
    size_t e4 = (size_t)blockIdx.x * 256 + threadIdx.x;   // float4 index
    size_t row = e4 >> 6;                                 // b*Nn + j
    float4 v = *(const float4*)&g_Wh[e4 * 4];
    float ep = g_E2p[row], en = g_E2n[row];
    float x1[4] = {v.x * ep, v.y * ep, v.z * ep, v.w * ep};
    float x2[4] = {v.x * en, v.y * en, v.z * en, v.w * en};
    float h1[4], h2[4];
#pragma unroll
    for (int k = 0; k < 4; k++) {
        h1[k] = __bfloat162float(__float2bfloat16(x1[k]));
        h2[k] = __bfloat162float(__float2bfloat16(x2[k]));
    }
    uint2 o;
    o.x = bf16pair(h1[0], h1[1]); o.y = bf16pair(h1[2], h1[3]);
    *(uint2*)&g_X1h[e4 * 4] = o;
    o.x = bf16pair(x1[0] - h1[0], x1[1] - h1[1]); o.y = bf16pair(x1[2] - h1[2], x1[3] - h1[3]);
    *(uint2*)&g_X1l[e4 * 4] = o;
    o.x = bf16pair(h2[0], h2[1]); o.y = bf16pair(h2[2], h2[3]);
    *(uint2*)&g_X2h[e4 * 4] = o;
    o.x = bf16pair(x2[0] - h2[0], x2[1] - h2[1]); o.y = bf16pair(x2[2] - h2[2], x2[3] - h2[3]);
    *(uint2*)&g_X2l[e4 * 4] = o;
}

// ---------------------------------------------------------------------------
// K4: packed bit masks + Z sums, vectorized (one warp per row, 4 j/lane/step)
// ---------------------------------------------------------------------------
__global__ __launch_bounds__(256) void mask_kernel(const float* __restrict__ adj) {
    int row = blockIdx.x * 8 + (threadIdx.x >> 5);
    int lane = threadIdx.x & 31;
    int b = row >> 11;
    const float4* ar  = (const float4*)(adj + (size_t)row * Nn);
    const float4* s2g = (const float4*)(g_S2 + b * Nn);
    const float4* epg = (const float4*)(g_E2p + b * Nn);
    const float4* eng = (const float4*)(g_E2n + b * Nn);
    float ns1 = -g_S1[row];
    float z1 = 0.f, z2 = 0.f;
    uint32_t w1lo = 0, w1hi = 0, w2lo = 0, w2hi = 0;
#pragma unroll 2
    for (int s = 0; s < 16; s++) {
        int q = s * 32 + lane;
        float4 av = ar[q];
        float4 sv = s2g[q];
        float4 pv = epg[q];
        float4 nv = eng[q];
        float avv[4] = {av.x, av.y, av.z, av.w};
        float svv[4] = {sv.x, sv.y, sv.z, sv.w};
        float pvv[4] = {pv.x, pv.y, pv.z, pv.w};
        float nvv[4] = {nv.x, nv.y, nv.z, nv.w};
        bool m1[4], m2[4];
#pragma unroll
        for (int t = 0; t < 4; t++) {
            bool on = avv[t] > 0.5f;
            bool pos = svv[t] > ns1;
            m1[t] = on && pos;
            m2[t] = on && !pos;
            if (m1[t]) z1 += pvv[t];
            if (m2[t]) z2 += nvv[t];
        }
#pragma unroll
        for (int t = 0; t < 4; t++) {
            uint32_t b1 = __ballot_sync(0xffffffffu, m1[t]);
            uint32_t b2 = __ballot_sync(0xffffffffu, m2[t]);
            int w = s * 4 + t;
            if (lane == (w & 31)) {
                if (w < 32) { w1lo = b1; w2lo = b2; }
                else        { w1hi = b1; w2hi = b2; }
            }
        }
    }
#pragma unroll
    for (int o = 16; o; o >>= 1) {
        z1 += __shfl_xor_sync(0xffffffffu, z1, o);
        z2 += __shfl_xor_sync(0xffffffffu, z2, o);
    }
    g_M1[(size_t)row * 64 + lane] = w1lo;
    g_M1[(size_t)row * 64 + 32 + lane] = w1hi;
    g_M2[(size_t)row * 64 + lane] = w2lo;
    g_M2[(size_t)row * 64 + 32 + lane] = w2hi;
    if (lane == 0) { g_Z1[row] = z1; g_Z2[row] = z2; }
}

// ---------------------------------------------------------------------------
// K5: HMMA masked attention + LayerNorm + exact GELU
//     CTA: 128 rows x 256 f, 512 threads, 16 warps (32x64 warp tiles)
//     3 X slots: write(chunk c) and prior reader MMA(c-3) are barrier-separated
// ---------------------------------------------------------------------------
#define ROWS 128
#define XS_STRIDE 260
#define SLOT_BYTES 32768                    // hi(16K)+lo(16K)
#define MEXP0 (3 * SLOT_BYTES)              // 98304
#define MSTRIDE 80
#define MEXP1 (MEXP0 + ROWS * MSTRIDE)      // 108544
#define PACKED_OFF (MEXP1 + ROWS * MSTRIDE) // 118784 (+32KB -> 151552)
#define DYN_B (PACKED_OFF + 32768)          // 151552 (xs overlay 133120 fits)

__global__ void __launch_bounds__(512, 1)
attn_mma_kernel(const float* __restrict__ gamma, const float* __restrict__ beta,
                float* __restrict__ out) {
    extern __shared__ char dyn[];
    __shared__ float e1p_s[ROWS], e1n_s[ROWS], invz_s[ROWS], mu_s[ROWS], rs_s[ROWS];

    const int tid = threadIdx.x;
    const int lane = tid & 31;
    const int wid = tid >> 5;
    const int wm = wid >> 2, wn = wid & 3;
    const int b = blockIdx.y;
    const int i0 = blockIdx.x * ROWS;

    const uint32_t smem = smem_u32(dyn);
    float* xs = (float*)dyn;
    uint32_t* packed_s = (uint32_t*)(dyn + PACKED_OFF);

    if (tid < ROWS) {
        float e1p = g_E1p[b * Nn + i0 + tid];
        float e1n = g_E1n[b * Nn + i0 + tid];
        e1p_s[tid] = e1p;
        e1n_s[tid] = e1n;
        invz_s[tid] = 1.f / (e1p * g_Z1[b * Nn + i0 + tid] +
                             e1n * g_Z2[b * Nn + i0 + tid]);
    }

    // ldmatrix per-lane address components (proven layout)
    const uint32_t aRowOff = (uint32_t)((32 * wm + ((lane >> 3) & 1) * 8 + (lane & 7)) * MSTRIDE
                                        + (lane >> 4) * 16);
    const int jb = ((lane >> 3) & 1) * 8 + (lane & 7);
    const int ub = 8 * wn + (lane >> 4);
    const int jsw = jb & 7;

    const int mi = tid >> 2;        // 0..127
    const int mq = tid & 3;
    const uint32_t mstRel = (uint32_t)(mi * MSTRIDE + mq * 16);

    const int r0 = 32 * wm + (lane >> 2);
    const int cb = 64 * wn + (lane & 3) * 2;
    float* gy = g_Wh + ((size_t)b * Nn + i0) * Fd;   // Y1 spill scratch

    float dacc[2][8][4];

#pragma unroll 1
    for (int pass = 0; pass < 2; pass++) {
        const unsigned short* srcH =
            (pass == 0 ? g_X1h : g_X2h) + (size_t)b * Nn * Fd;
        const unsigned short* srcL =
            (pass == 0 ? g_X1l : g_X2l) + (size_t)b * Nn * Fd;
        const uint32_t* gM =
            (pass == 0 ? g_M1 : g_M2) + (size_t)(b * Nn + i0) * 64;

#pragma unroll
        for (int mt = 0; mt < 2; mt++)
#pragma unroll
            for (int n8 = 0; n8 < 8; n8++)
#pragma unroll
                for (int k = 0; k < 4; k++) dacc[mt][n8][k] = 0.f;

        // load packed masks (8192 words = 2048 uint4)
#pragma unroll
        for (int r = 0; r < 4; r++) {
            int idx = tid + r * 512;
            *(uint4*)&packed_s[idx * 4] = ((const uint4*)gM)[idx];
        }

        // prologue cp: chunk 0 -> slot 0
#pragma unroll
        for (int r = 0; r < 2; r++) {
            int e = tid + r * 512;
            int j = e >> 5, u = e & 31;
            uint32_t d = smem + j * 512 + ((u ^ (j & 7)) << 4);
            cp_async16(d, srcH + (size_t)j * Fd + u * 8);
            cp_async16(d + 16384, srcL + (size_t)j * Fd + u * 8);
        }
        cp_commit();
        __syncthreads();   // packed masks visible

        // expand mask chunk 0 -> buf0
        {
            uint4 wv = *(const uint4*)&packed_s[mi * 64];
            uint32_t sh = (uint32_t)(mq << 1);
            uint32_t w0 = ((wv.x >> sh) & 1u) * 0x3F80u + ((wv.y >> sh) & 1u) * 0x3F800000u;
            uint32_t w1 = ((wv.z >> sh) & 1u) * 0x3F80u + ((wv.w >> sh) & 1u) * 0x3F800000u;
            uint32_t w2 = ((wv.x >> (sh + 1)) & 1u) * 0x3F80u + ((wv.y >> (sh + 1)) & 1u) * 0x3F800000u;
            uint32_t w3 = ((wv.z >> (sh + 1)) & 1u) * 0x3F80u + ((wv.w >> (sh + 1)) & 1u) * 0x3F800000u;
            asm volatile("st.shared.v4.b32 [%0], {%1,%2,%3,%4};"
                         :: "r"(smem + MEXP0 + mstRel), "r"(w0), "r"(w1), "r"(w2), "r"(w3) : "memory");
        }

        int cur = 0;   // slot of chunk it (it % 3)
#pragma unroll 1
        for (int it = 0; it < NIT; it++) {
            // issue X(it+1) into slot (it+1)%3
            if (it + 1 < NIT) {
                int nxt = cur + 1; if (nxt == 3) nxt = 0;
                uint32_t dst = smem + (uint32_t)nxt * SLOT_BYTES;
                size_t grow = (size_t)((it + 1) * KC) * Fd;
#pragma unroll
                for (int r = 0; r < 2; r++) {
                    int e = tid + r * 512;
                    int j = e >> 5, u = e & 31;
                    uint32_t d = dst + j * 512 + ((u ^ (j & 7)) << 4);
                    cp_async16(d, srcH + grow + (size_t)j * Fd + u * 8);
                    cp_async16(d + 16384, srcL + grow + (size_t)j * Fd + u * 8);
                }
            }
            cp_commit();
            cp_wait1();        // X(it) landed
            __syncthreads();   // mask(it) writes + X(it) visible to all

            // MMA on chunk it
            const uint32_t xb = smem + (uint32_t)cur * SLOT_BYTES;
            const uint32_t mbuf = smem + ((it & 1) ? MEXP1 : MEXP0);
#pragma unroll
            for (int ks = 0; ks < 2; ks++) {
                uint32_t a0[4], a1[4];
                ldsm4(a0, mbuf + aRowOff + ks * 32);
                ldsm4(a1, mbuf + aRowOff + 16 * MSTRIDE + ks * 32);
                const int j = jb + ks * 16;
                const uint32_t rowb = xb + j * 512;
#pragma unroll
                for (int ng = 0; ng < 4; ng++) {
                    const int u = ub + 2 * ng;
                    const uint32_t addrH = rowb + ((u ^ jsw) << 4);
                    uint32_t bh[4], bl[4];
                    ldsm4t(bh, addrH);
                    ldsm4t(bl, addrH + 16384);
                    mma16816(dacc[0][2 * ng],     a0, bh[0], bh[1]);
                    mma16816(dacc[0][2 * ng + 1], a0, bh[2], bh[3]);
                    mma16816(dacc[1][2 * ng],     a1, bh[0], bh[1]);
                    mma16816(dacc[1][2 * ng + 1], a1, bh[2], bh[3]);
                    mma16816(dacc[0][2 * ng],     a0, bl[0], bl[1]);
                    mma16816(dacc[0][2 * ng + 1], a0, bl[2], bl[3]);
                    mma16816(dacc[1][2 * ng],     a1, bl[0], bl[1]);
                    mma16816(dacc[1][2 * ng + 1], a1, bl[2], bl[3]);
                }
            }

            // expand mask(it+1) into the other buffer (its previous readers
            // finished before barrier(it))
            if (it + 1 < NIT) {
                int cc = it + 1;
                uint4 wv = *(const uint4*)&packed_s[mi * 64 + ((cc >> 2) << 2)];
                uint32_t sh = (uint32_t)(((cc & 3) << 3) + (mq << 1));
                uint32_t w0 = ((wv.x >> sh) & 1u) * 0x3F80u + ((wv.y >> sh) & 1u) * 0x3F800000u;
                uint32_t w1 = ((wv.z >> sh) & 1u) * 0x3F80u + ((wv.w >> sh) & 1u) * 0x3F800000u;
                uint32_t w2 = ((wv.x >> (sh + 1)) & 1u) * 0x3F80u + ((wv.y >> (sh + 1)) & 1u) * 0x3F800000u;
                uint32_t w3 = ((wv.z >> (sh + 1)) & 1u) * 0x3F80u + ((wv.w >> (sh + 1)) & 1u) * 0x3F800000u;
                uint32_t dst = smem + ((cc & 1) ? MEXP1 : MEXP0) + mstRel;
                asm volatile("st.shared.v4.b32 [%0], {%1,%2,%3,%4};"
                             :: "r"(dst), "r"(w0), "r"(w1), "r"(w2), "r"(w3) : "memory");
            }
            cur = cur + 1; if (cur == 3) cur = 0;
        }
        __syncthreads();   // all MMA reads + expands done before pass flip

        if (pass == 0) {
            // spill e1p*Y1 to global scratch (thread-private addresses)
#pragma unroll
            for (int mt = 0; mt < 2; mt++) {
                int ra = r0 + 16 * mt;
                float ea = e1p_s[ra], eb = e1p_s[ra + 8];
#pragma unroll
                for (int n8 = 0; n8 < 8; n8++) {
                    int c = cb + 8 * n8;
                    *(float2*)&gy[(size_t)ra * 256 + c] =
                        make_float2(ea * dacc[mt][n8][0], ea * dacc[mt][n8][1]);
                    *(float2*)&gy[(size_t)(ra + 8) * 256 + c] =
                        make_float2(eb * dacc[mt][n8][2], eb * dacc[mt][n8][3]);
                }
            }
        }
    }

    // combine: x = (gy + e1n*Y2) * invZ -> xs (overlays main-loop smem)
#pragma unroll
    for (int mt = 0; mt < 2; mt++) {
        int ra = r0 + 16 * mt;
        float ea = e1n_s[ra], eb = e1n_s[ra + 8];
        float iza = invz_s[ra], izb = invz_s[ra + 8];
#pragma unroll
        for (int n8 = 0; n8 < 8; n8++) {
            int c = cb + 8 * n8;
            float2 ya = *(const float2*)&gy[(size_t)ra * 256 + c];
            float2 yb = *(const float2*)&gy[(size_t)(ra + 8) * 256 + c];
            xs[ra * XS_STRIDE + c]     = (ya.x + ea * dacc[mt][n8][0]) * iza;
            xs[ra * XS_STRIDE + c + 1] = (ya.y + ea * dacc[mt][n8][1]) * iza;
            xs[(ra + 8) * XS_STRIDE + c]     = (yb.x + eb * dacc[mt][n8][2]) * izb;
            xs[(ra + 8) * XS_STRIDE + c + 1] = (yb.y + eb * dacc[mt][n8][3]) * izb;
        }
    }
    __syncthreads();

    // LayerNorm stats: 4 threads per row
    {
        int row = tid >> 2, q = tid & 3;
        const float* xr = &xs[row * XS_STRIDE + q * 64];
        float sum = 0.f, ssq = 0.f;
#pragma unroll 8
        for (int k = 0; k < 64; k++) { float v = xr[k]; sum += v; ssq += v * v; }
        sum += __shfl_xor_sync(0xffffffffu, sum, 1);
        sum += __shfl_xor_sync(0xffffffffu, sum, 2);
        ssq += __shfl_xor_sync(0xffffffffu, ssq, 1);
        ssq += __shfl_xor_sync(0xffffffffu, ssq, 2);
        if (q == 0) {
            float mu = sum * (1.f / 256.f);
            float var = fmaxf(ssq * (1.f / 256.f) - mu * mu, 0.f);
            mu_s[row] = mu;
            rs_s[row] = rsqrtf(var + 1e-5f);
        }
    }
    __syncthreads();

    // gamma/beta + exact GELU, coalesced store (128 rows x 64 float4 = 8192)
    float* outb = out + ((size_t)b * Nn + i0) * Fd;
#pragma unroll 1
    for (int r = 0; r < 16; r++) {
        int u = tid + r * 512;
        int i = u >> 6;
        int c4 = (u & 63) * 4;
        float mu = mu_s[i], rs = rs_s[i];
        float4 xv = *(const float4*)&xs[i * XS_STRIDE + c4];
        float4 g = *(const float4*)&gamma[c4];
        float4 be = *(const float4*)&beta[c4];
        float x[4] = {xv.x, xv.y, xv.z, xv.w};
        float gv[4] = {g.x, g.y, g.z, g.w};
        float bv[4] = {be.x, be.y, be.z, be.w};
        float ov[4];
#pragma unroll
        for (int e = 0; e < 4; e++) {
            float y = (x[e] - mu) * rs * gv[e] + bv[e];
            ov[e] = 0.5f * y * (1.f + erff(y * 0.7071067811865475f));
        }
        *(float4*)&outb[(size_t)i * 256 + c4] = make_float4(ov[0], ov[1], ov[2], ov[3]);
    }
}

// ---------------------------------------------------------------------------
extern "C" void kernel_launch(void* const* d_in, const int* in_sizes, int n_in,
                              void* d_out, int out_size) {
    const float* h     = (const float*)d_in[0];
    const float* adj   = (const float*)d_in[1];
    const float* W     = (const float*)d_in[2];
    const float* a     = (const float*)d_in[3];
    const float* gamma = (const float*)d_in[4];
    const float* beta  = (const float*)d_in[5];
    float* out = (float*)d_out;

    cudaFuncSetAttribute(attn_mma_kernel,
                         cudaFuncAttributeMaxDynamicSharedMemorySize, DYN_B);

    gemm1_kernel<<<dim3(256, 4), 256>>>(h, W);
    score_kernel<<<2048, 256>>>(a);
    buildX_kernel<<<4096, 256>>>();
    mask_kernel<<<2048, 256>>>(adj);
    attn_mma_kernel<<<dim3(16, 8), 512, DYN_B>>>(gamma, beta, out);
}

// round 11
// speedup vs baseline: 1.2580x; 1.0031x over previous
#include <cuda_runtime.h>
#include <cuda_bf16.h>
#include <cstdint>

#define Bsz 8
#define Nn 2048
#define Fd 256
#define KC 32
#define NIT (Nn / KC)   // 64 chunks per pass

// -------- device scratch (no allocation allowed) --------
__device__ float g_Wh[(size_t)Bsz * Nn * Fd];      // Wh, later reused as Y1 spill
__device__ float g_S1[Bsz * Nn];
__device__ float g_S2[Bsz * Nn];
__device__ float g_E1p[Bsz * Nn];
__device__ float g_E1n[Bsz * Nn];
__device__ float g_E2p[Bsz * Nn];
__device__ float g_E2n[Bsz * Nn];
__device__ float g_Z1[Bsz * Nn];
__device__ float g_Z2[Bsz * Nn];
// X arrays, layout [b][j][f], bf16
__device__ unsigned short g_X1h[(size_t)Bsz * Nn * Fd];
__device__ unsigned short g_X1l[(size_t)Bsz * Nn * Fd];
__device__ unsigned short g_X2h[(size_t)Bsz * Nn * Fd];
__device__ unsigned short g_X2l[(size_t)Bsz * Nn * Fd];
// packed bit masks: [row][64] u32; word w = s*4+t holds bit l = mask at
// j = s*128 + 4*l + t
__device__ uint32_t g_M1[(size_t)Bsz * Nn * 64];
__device__ uint32_t g_M2[(size_t)Bsz * Nn * 64];

// -------- helpers --------
__device__ __forceinline__ uint32_t smem_u32(const void* p) {
    uint32_t a;
    asm("{ .reg .u64 t; cvta.to.shared.u64 t, %1; cvt.u32.u64 %0, t; }" : "=r"(a) : "l"(p));
    return a;
}
__device__ __forceinline__ void cp_async16(uint32_t dst, const void* src) {
    asm volatile("cp.async.cg.shared.global [%0], [%1], 16;" :: "r"(dst), "l"(src) : "memory");
}
__device__ __forceinline__ void cp_commit() {
    asm volatile("cp.async.commit_group;" ::: "memory");
}
__device__ __forceinline__ void cp_wait1() {
    asm volatile("cp.async.wait_group 1;" ::: "memory");
}
__device__ __forceinline__ void ldsm4(uint32_t* r, uint32_t addr) {
    asm volatile("ldmatrix.sync.aligned.m8n8.x4.shared.b16 {%0,%1,%2,%3}, [%4];"
                 : "=r"(r[0]), "=r"(r[1]), "=r"(r[2]), "=r"(r[3]) : "r"(addr));
}
__device__ __forceinline__ void ldsm4t(uint32_t* r, uint32_t addr) {
    asm volatile("ldmatrix.sync.aligned.m8n8.x4.trans.shared.b16 {%0,%1,%2,%3}, [%4];"
                 : "=r"(r[0]), "=r"(r[1]), "=r"(r[2]), "=r"(r[3]) : "r"(addr));
}
__device__ __forceinline__ void mma16816(float* d, const uint32_t* a, uint32_t b0, uint32_t b1) {
    asm volatile(
        "mma.sync.aligned.m16n8k16.row.col.f32.bf16.bf16.f32 "
        "{%0,%1,%2,%3}, {%4,%5,%6,%7}, {%8,%9}, {%0,%1,%2,%3};"
        : "+f"(d[0]), "+f"(d[1]), "+f"(d[2]), "+f"(d[3])
        : "r"(a[0]), "r"(a[1]), "r"(a[2]), "r"(a[3]), "r"(b0), "r"(b1));
}
__device__ __forceinline__ uint32_t bf16pair(float lo, float hi) {
    uint32_t r;
    asm("cvt.rn.bf16x2.f32 %0, %1, %2;" : "=r"(r) : "f"(hi), "f"(lo));
    return r;
}

// ---------------------------------------------------------------------------
// K1: Wh = h @ W  (fp32, known-good, at scalar-FFMA ceiling)
// ---------------------------------------------------------------------------
__global__ __launch_bounds__(256) void gemm1_kernel(const float* __restrict__ h,
                                                    const float* __restrict__ W) {
    __shared__ float As[16][68];
    __shared__ float Bs[16][64];
    int tid = threadIdx.x;
    int i0 = blockIdx.x * 64, f0 = blockIdx.y * 64;
    int tx = tid & 15, ty = tid >> 4;
    float acc[4][4] = {};
    for (int k0 = 0; k0 < 256; k0 += 16) {
        {
            int r = tid >> 2, c4 = (tid & 3) * 4;
            float4 v = *(const float4*)&h[(size_t)(i0 + r) * 256 + k0 + c4];
            As[c4 + 0][r] = v.x; As[c4 + 1][r] = v.y;
            As[c4 + 2][r] = v.z; As[c4 + 3][r] = v.w;
        }
        {
            int r = tid >> 4, c4 = (tid & 15) * 4;
            *(float4*)&Bs[r][c4] = *(const float4*)&W[(size_t)(k0 + r) * 256 + f0 + c4];
        }
        __syncthreads();
#pragma unroll
        for (int k = 0; k < 16; k++) {
            float4 a = *(const float4*)&As[k][ty * 4];
            float4 b = *(const float4*)&Bs[k][tx * 4];
            float av[4] = {a.x, a.y, a.z, a.w};
            float bv[4] = {b.x, b.y, b.z, b.w};
#pragma unroll
            for (int ii = 0; ii < 4; ii++)
#pragma unroll
                for (int jj = 0; jj < 4; jj++) acc[ii][jj] += av[ii] * bv[jj];
        }
        __syncthreads();
    }
#pragma unroll
    for (int ii = 0; ii < 4; ii++)
        *(float4*)&g_Wh[(size_t)(i0 + ty * 4 + ii) * 256 + f0 + tx * 4] =
            make_float4(acc[ii][0], acc[ii][1], acc[ii][2], acc[ii][3]);
}

// ---------------------------------------------------------------------------
// K2: scores + factored exps
// ---------------------------------------------------------------------------
__global__ __launch_bounds__(256) void score_kernel(const float* __restrict__ a) {
    int row = blockIdx.x * 8 + (threadIdx.x >> 5);
    int lane = threadIdx.x & 31;
    const float* wh = &g_Wh[(size_t)row * 256];
    float s1 = 0.f, s2 = 0.f;
#pragma unroll
    for (int c = 0; c < 8; c++) {
        int f = c * 32 + lane;
        float v = wh[f];
        s1 += v * a[f];
        s2 += v * a[256 + f];
    }
#pragma unroll
    for (int o = 16; o; o >>= 1) {
        s1 += __shfl_xor_sync(0xffffffffu, s1, o);
        s2 += __shfl_xor_sync(0xffffffffu, s2, o);
    }
    if (lane == 0) {
        g_S1[row] = s1; g_S2[row] = s2;
        g_E1p[row] = expf(s1);  g_E1n[row] = expf(0.2f * s1);
        g_E2p[row] = expf(s2);  g_E2n[row] = expf(0.2f * s2);
    }
}

// ---------------------------------------------------------------------------
// K3: X1/X2 hi/lo bf16 split (4096 blocks x 256 thr)
// ---------------------------------------------------------------------------
__global__ __launch_bounds__(256) void buildX_kernel() {
    size_t e4 = (size_t)blockIdx.x * 256 + threadIdx.x;   // float4 index
    size_t row = e4 >> 6;                                 // b*Nn + j
    float4 v = *(const float4*)&g_Wh[e4 * 4];
    float ep = g_E2p[row], en = g_E2n[row];
    float x1[4] = {v.x * ep, v.y * ep, v.z * ep, v.w * ep};
    float x2[4] = {v.x * en, v.y * en, v.z * en, v.w * en};
    float h1[4], h2[4];
#pragma unroll
    for (int k = 0; k < 4; k++) {
        h1[k] = __bfloat162float(__float2bfloat16(x1[k]));
        h2[k] = __bfloat162float(__float2bfloat16(x2[k]));
    }
    uint2 o;
    o.x = bf16pair(h1[0], h1[1]); o.y = bf16pair(h1[2], h1[3]);
    *(uint2*)&g_X1h[e4 * 4] = o;
    o.x = bf16pair(x1[0] - h1[0], x1[1] - h1[1]); o.y = bf16pair(x1[2] - h1[2], x1[3] - h1[3]);
    *(uint2*)&g_X1l[e4 * 4] = o;
    o.x = bf16pair(h2[0], h2[1]); o.y = bf16pair(h2[2], h2[3]);
    *(uint2*)&g_X2h[e4 * 4] = o;
    o.x = bf16pair(x2[0] - h2[0], x2[1] - h2[1]); o.y = bf16pair(x2[2] - h2[2], x2[3] - h2[3]);
    *(uint2*)&g_X2l[e4 * 4] = o;
}

// ---------------------------------------------------------------------------
// K4: packed bit masks + Z sums, vectorized (one warp per row, 4 j/lane/step)
// ---------------------------------------------------------------------------
__global__ __launch_bounds__(256) void mask_kernel(const float* __restrict__ adj) {
    int row = blockIdx.x * 8 + (threadIdx.x >> 5);
    int lane = threadIdx.x & 31;
    int b = row >> 11;
    const float4* ar  = (const float4*)(adj + (size_t)row * Nn);
    const float4* s2g = (const float4*)(g_S2 + b * Nn);
    const float4* epg = (const float4*)(g_E2p + b * Nn);
    const float4* eng = (const float4*)(g_E2n + b * Nn);
    float ns1 = -g_S1[row];
    float z1 = 0.f, z2 = 0.f;
    uint32_t w1lo = 0, w1hi = 0, w2lo = 0, w2hi = 0;
#pragma unroll 2
    for (int s = 0; s < 16; s++) {
        int q = s * 32 + lane;
        float4 av = ar[q];
        float4 sv = s2g[q];
        float4 pv = epg[q];
        float4 nv = eng[q];
        float avv[4] = {av.x, av.y, av.z, av.w};
        float svv[4] = {sv.x, sv.y, sv.z, sv.w};
        float pvv[4] = {pv.x, pv.y, pv.z, pv.w};
        float nvv[4] = {nv.x, nv.y, nv.z, nv.w};
        bool m1[4], m2[4];
#pragma unroll
        for (int t = 0; t < 4; t++) {
            bool on = avv[t] > 0.5f;
            bool pos = svv[t] > ns1;
            m1[t] = on && pos;
            m2[t] = on && !pos;
            if (m1[t]) z1 += pvv[t];
            if (m2[t]) z2 += nvv[t];
        }
#pragma unroll
        for (int t = 0; t < 4; t++) {
            uint32_t b1 = __ballot_sync(0xffffffffu, m1[t]);
            uint32_t b2 = __ballot_sync(0xffffffffu, m2[t]);
            int w = s * 4 + t;
            if (lane == (w & 31)) {
                if (w < 32) { w1lo = b1; w2lo = b2; }
                else        { w1hi = b1; w2hi = b2; }
            }
        }
    }
#pragma unroll
    for (int o = 16; o; o >>= 1) {
        z1 += __shfl_xor_sync(0xffffffffu, z1, o);
        z2 += __shfl_xor_sync(0xffffffffu, z2, o);
    }
    g_M1[(size_t)row * 64 + lane] = w1lo;
    g_M1[(size_t)row * 64 + 32 + lane] = w1hi;
    g_M2[(size_t)row * 64 + lane] = w2lo;
    g_M2[(size_t)row * 64 + 32 + lane] = w2hi;
    if (lane == 0) { g_Z1[row] = z1; g_Z2[row] = z2; }
}

// ---------------------------------------------------------------------------
// K5: HMMA masked attention + LayerNorm + exact GELU
//     CTA: 128 rows x 256 f, 512 threads, 16 warps (32x64 warp tiles)
//     3 X slots, 2-chunk lookahead: issue(it+2) AFTER bar(it), so the slot's
//     previous readers (MMA(it-1)) are barrier-separated.
// ---------------------------------------------------------------------------
#define ROWS 128
#define XS_STRIDE 260
#define SLOT_BYTES 32768                    // hi(16K)+lo(16K)
#define MEXP0 (3 * SLOT_BYTES)              // 98304
#define MSTRIDE 80
#define MEXP1 (MEXP0 + ROWS * MSTRIDE)      // 108544
#define PACKED_OFF (MEXP1 + ROWS * MSTRIDE) // 118784 (+32KB -> 151552)
#define DYN_B (PACKED_OFF + 32768)          // 151552 (xs overlay 133120 fits)

__global__ void __launch_bounds__(512, 1)
attn_mma_kernel(const float* __restrict__ gamma, const float* __restrict__ beta,
                float* __restrict__ out) {
    extern __shared__ char dyn[];
    __shared__ float e1p_s[ROWS], e1n_s[ROWS], invz_s[ROWS], mu_s[ROWS], rs_s[ROWS];

    const int tid = threadIdx.x;
    const int lane = tid & 31;
    const int wid = tid >> 5;
    const int wm = wid >> 2, wn = wid & 3;
    const int b = blockIdx.y;
    const int i0 = blockIdx.x * ROWS;

    const uint32_t smem = smem_u32(dyn);
    float* xs = (float*)dyn;
    uint32_t* packed_s = (uint32_t*)(dyn + PACKED_OFF);

    if (tid < ROWS) {
        float e1p = g_E1p[b * Nn + i0 + tid];
        float e1n = g_E1n[b * Nn + i0 + tid];
        e1p_s[tid] = e1p;
        e1n_s[tid] = e1n;
        invz_s[tid] = 1.f / (e1p * g_Z1[b * Nn + i0 + tid] +
                             e1n * g_Z2[b * Nn + i0 + tid]);
    }

    // ldmatrix per-lane address components (proven layout)
    const uint32_t aRowOff = (uint32_t)((32 * wm + ((lane >> 3) & 1) * 8 + (lane & 7)) * MSTRIDE
                                        + (lane >> 4) * 16);
    const int jb = ((lane >> 3) & 1) * 8 + (lane & 7);
    const int ub = 8 * wn + (lane >> 4);
    const int jsw = jb & 7;

    const int mi = tid >> 2;        // 0..127
    const int mq = tid & 3;
    const uint32_t mstRel = (uint32_t)(mi * MSTRIDE + mq * 16);

    const int r0 = 32 * wm + (lane >> 2);
    const int cb = 64 * wn + (lane & 3) * 2;
    float* gy = g_Wh + ((size_t)b * Nn + i0) * Fd;   // Y1 spill scratch

    float dacc[2][8][4];

#pragma unroll 1
    for (int pass = 0; pass < 2; pass++) {
        const unsigned short* srcH =
            (pass == 0 ? g_X1h : g_X2h) + (size_t)b * Nn * Fd;
        const unsigned short* srcL =
            (pass == 0 ? g_X1l : g_X2l) + (size_t)b * Nn * Fd;
        const uint32_t* gM =
            (pass == 0 ? g_M1 : g_M2) + (size_t)(b * Nn + i0) * 64;

#pragma unroll
        for (int mt = 0; mt < 2; mt++)
#pragma unroll
            for (int n8 = 0; n8 < 8; n8++)
#pragma unroll
                for (int k = 0; k < 4; k++) dacc[mt][n8][k] = 0.f;

        // load packed masks (8192 words = 2048 uint4)
#pragma unroll
        for (int r = 0; r < 4; r++) {
            int idx = tid + r * 512;
            *(uint4*)&packed_s[idx * 4] = ((const uint4*)gM)[idx];
        }

        // prologue: issue chunk 0 -> slot 0, chunk 1 -> slot 1 (2 groups)
#pragma unroll
        for (int c0 = 0; c0 < 2; c0++) {
            uint32_t dst = smem + (uint32_t)c0 * SLOT_BYTES;
            size_t grow = (size_t)(c0 * KC) * Fd;
#pragma unroll
            for (int r = 0; r < 2; r++) {
                int e = tid + r * 512;
                int j = e >> 5, u = e & 31;
                uint32_t d = dst + j * 512 + ((u ^ (j & 7)) << 4);
                cp_async16(d, srcH + grow + (size_t)j * Fd + u * 8);
                cp_async16(d + 16384, srcL + grow + (size_t)j * Fd + u * 8);
            }
            cp_commit();
        }
        __syncthreads();   // packed masks visible

        // expand mask chunk 0 -> buf0
        {
            uint4 wv = *(const uint4*)&packed_s[mi * 64];
            uint32_t sh = (uint32_t)(mq << 1);
            uint32_t w0 = ((wv.x >> sh) & 1u) * 0x3F80u + ((wv.y >> sh) & 1u) * 0x3F800000u;
            uint32_t w1 = ((wv.z >> sh) & 1u) * 0x3F80u + ((wv.w >> sh) & 1u) * 0x3F800000u;
            uint32_t w2 = ((wv.x >> (sh + 1)) & 1u) * 0x3F80u + ((wv.y >> (sh + 1)) & 1u) * 0x3F800000u;
            uint32_t w3 = ((wv.z >> (sh + 1)) & 1u) * 0x3F80u + ((wv.w >> (sh + 1)) & 1u) * 0x3F800000u;
            asm volatile("st.shared.v4.b32 [%0], {%1,%2,%3,%4};"
                         :: "r"(smem + MEXP0 + mstRel), "r"(w0), "r"(w1), "r"(w2), "r"(w3) : "memory");
        }

#pragma unroll 1
        for (int it = 0; it < NIT; it++) {
            cp_wait1();        // X(it) landed (2 groups pending -> wait to <=1)
            __syncthreads();   // X(it) + mask(it) visible to all; MMA(it-1) done

            // issue X(it+2) into slot (it+2)%3 = slot (it-1)%3 (readers done)
            {
                int c2 = it + 2;
                if (c2 < NIT) {
                    int s2 = c2 % 3;
                    uint32_t dst = smem + (uint32_t)s2 * SLOT_BYTES;
                    size_t grow = (size_t)(c2 * KC) * Fd;
#pragma unroll
                    for (int r = 0; r < 2; r++) {
                        int e = tid + r * 512;
                        int j = e >> 5, u = e & 31;
                        uint32_t d = dst + j * 512 + ((u ^ (j & 7)) << 4);
                        cp_async16(d, srcH + grow + (size_t)j * Fd + u * 8);
                        cp_async16(d + 16384, srcL + grow + (size_t)j * Fd + u * 8);
                    }
                }
                cp_commit();   // always commit to keep group accounting uniform
            }

            // MMA on chunk it
            const uint32_t xb = smem + (uint32_t)(it % 3) * SLOT_BYTES;
            const uint32_t mbuf = smem + ((it & 1) ? MEXP1 : MEXP0);
#pragma unroll
            for (int ks = 0; ks < 2; ks++) {
                uint32_t a0[4], a1[4];
                ldsm4(a0, mbuf + aRowOff + ks * 32);
                ldsm4(a1, mbuf + aRowOff + 16 * MSTRIDE + ks * 32);
                const int j = jb + ks * 16;
                const uint32_t rowb = xb + j * 512;
#pragma unroll
                for (int ng = 0; ng < 4; ng++) {
                    const int u = ub + 2 * ng;
                    const uint32_t addrH = rowb + ((u ^ jsw) << 4);
                    uint32_t bh[4], bl[4];
                    ldsm4t(bh, addrH);
                    ldsm4t(bl, addrH + 16384);
                    mma16816(dacc[0][2 * ng],     a0, bh[0], bh[1]);
                    mma16816(dacc[0][2 * ng + 1], a0, bh[2], bh[3]);
                    mma16816(dacc[1][2 * ng],     a1, bh[0], bh[1]);
                    mma16816(dacc[1][2 * ng + 1], a1, bh[2], bh[3]);
                    mma16816(dacc[0][2 * ng],     a0, bl[0], bl[1]);
                    mma16816(dacc[0][2 * ng + 1], a0, bl[2], bl[3]);
                    mma16816(dacc[1][2 * ng],     a1, bl[0], bl[1]);
                    mma16816(dacc[1][2 * ng + 1], a1, bl[2], bl[3]);
                }
            }

            // expand mask(it+1) into the other buffer (its previous readers
            // MMA(it-1) finished before bar(it))
            if (it + 1 < NIT) {
                int cc = it + 1;
                uint4 wv = *(const uint4*)&packed_s[mi * 64 + ((cc >> 2) << 2)];
                uint32_t sh = (uint32_t)(((cc & 3) << 3) + (mq << 1));
                uint32_t w0 = ((wv.x >> sh) & 1u) * 0x3F80u + ((wv.y >> sh) & 1u) * 0x3F800000u;
                uint32_t w1 = ((wv.z >> sh) & 1u) * 0x3F80u + ((wv.w >> sh) & 1u) * 0x3F800000u;
                uint32_t w2 = ((wv.x >> (sh + 1)) & 1u) * 0x3F80u + ((wv.y >> (sh + 1)) & 1u) * 0x3F800000u;
                uint32_t w3 = ((wv.z >> (sh + 1)) & 1u) * 0x3F80u + ((wv.w >> (sh + 1)) & 1u) * 0x3F800000u;
                uint32_t dst = smem + ((cc & 1) ? MEXP1 : MEXP0) + mstRel;
                asm volatile("st.shared.v4.b32 [%0], {%1,%2,%3,%4};"
                             :: "r"(dst), "r"(w0), "r"(w1), "r"(w2), "r"(w3) : "memory");
            }
        }
        __syncthreads();   // all MMA reads + expands done before pass flip

        if (pass == 0) {
            // spill e1p*Y1 to global scratch (thread-private addresses)
#pragma unroll
            for (int mt = 0; mt < 2; mt++) {
                int ra = r0 + 16 * mt;
                float ea = e1p_s[ra], eb = e1p_s[ra + 8];
#pragma unroll
                for (int n8 = 0; n8 < 8; n8++) {
                    int c = cb + 8 * n8;
                    *(float2*)&gy[(size_t)ra * 256 + c] =
                        make_float2(ea * dacc[mt][n8][0], ea * dacc[mt][n8][1]);
                    *(float2*)&gy[(size_t)(ra + 8) * 256 + c] =
                        make_float2(eb * dacc[mt][n8][2], eb * dacc[mt][n8][3]);
                }
            }
        }
    }

    // combine: x = (gy + e1n*Y2) * invZ -> xs (overlays main-loop smem)
#pragma unroll
    for (int mt = 0; mt < 2; mt++) {
        int ra = r0 + 16 * mt;
        float ea = e1n_s[ra], eb = e1n_s[ra + 8];
        float iza = invz_s[ra], izb = invz_s[ra + 8];
#pragma unroll
        for (int n8 = 0; n8 < 8; n8++) {
            int c = cb + 8 * n8;
            float2 ya = *(const float2*)&gy[(size_t)ra * 256 + c];
            float2 yb = *(const float2*)&gy[(size_t)(ra + 8) * 256 + c];
            xs[ra * XS_STRIDE + c]     = (ya.x + ea * dacc[mt][n8][0]) * iza;
            xs[ra * XS_STRIDE + c + 1] = (ya.y + ea * dacc[mt][n8][1]) * iza;
            xs[(ra + 8) * XS_STRIDE + c]     = (yb.x + eb * dacc[mt][n8][2]) * izb;
            xs[(ra + 8) * XS_STRIDE + c + 1] = (yb.y + eb * dacc[mt][n8][3]) * izb;
        }
    }
    __syncthreads();

    // LayerNorm stats: 4 threads per row (float4 LDS)
    {
        int row = tid >> 2, q = tid & 3;
        const float4* xr = (const float4*)&xs[row * XS_STRIDE + q * 64];
        float sum = 0.f, ssq = 0.f;
#pragma unroll
        for (int k = 0; k < 16; k++) {
            float4 v = xr[k];
            sum += v.x + v.y + v.z + v.w;
            ssq += v.x * v.x + v.y * v.y + v.z * v.z + v.w * v.w;
        }
        sum += __shfl_xor_sync(0xffffffffu, sum, 1);
        sum += __shfl_xor_sync(0xffffffffu, sum, 2);
        ssq += __shfl_xor_sync(0xffffffffu, ssq, 1);
        ssq += __shfl_xor_sync(0xffffffffu, ssq, 2);
        if (q == 0) {
            float mu = sum * (1.f / 256.f);
            float var = fmaxf(ssq * (1.f / 256.f) - mu * mu, 0.f);
            mu_s[row] = mu;
            rs_s[row] = rsqrtf(var + 1e-5f);
        }
    }
    __syncthreads();

    // gamma/beta + exact GELU, coalesced store (128 rows x 64 float4 = 8192)
    float* outb = out + ((size_t)b * Nn + i0) * Fd;
#pragma unroll 1
    for (int r = 0; r < 16; r++) {
        int u = tid + r * 512;
        int i = u >> 6;
        int c4 = (u & 63) * 4;
        float mu = mu_s[i], rs = rs_s[i];
        float4 xv = *(const float4*)&xs[i * XS_STRIDE + c4];
        float4 g = *(const float4*)&gamma[c4];
        float4 be = *(const float4*)&beta[c4];
        float x[4] = {xv.x, xv.y, xv.z, xv.w};
        float gv[4] = {g.x, g.y, g.z, g.w};
        float bv[4] = {be.x, be.y, be.z, be.w};
        float ov[4];
#pragma unroll
        for (int e = 0; e < 4; e++) {
            float y = (x[e] - mu) * rs * gv[e] + bv[e];
            ov[e] = 0.5f * y * (1.f + erff(y * 0.7071067811865475f));
        }
        *(float4*)&outb[(size_t)i * 256 + c4] = make_float4(ov[0], ov[1], ov[2], ov[3]);
    }
}

// ---------------------------------------------------------------------------
extern "C" void kernel_launch(void* const* d_in, const int* in_sizes, int n_in,
                              void* d_out, int out_size) {
    const float* h     = (const float*)d_in[0];
    const float* adj   = (const float*)d_in[1];
    const float* W     = (const float*)d_in[2];
    const float* a     = (const float*)d_in[3];
    const float* gamma = (const float*)d_in[4];
    const float* beta  = (const float*)d_in[5];
    float* out = (float*)d_out;

    cudaFuncSetAttribute(attn_mma_kernel,
                         cudaFuncAttributeMaxDynamicSharedMemorySize, DYN_B);

    gemm1_kernel<<<dim3(256, 4), 256>>>(h, W);
    score_kernel<<<2048, 256>>>(a);
    buildX_kernel<<<4096, 256>>>();
    mask_kernel<<<2048, 256>>>(adj);
    attn_mma_kernel<<<dim3(16, 8), 512, DYN_B>>>(gamma, beta, out);
}